// round 15
// baseline (speedup 1.0000x reference)
#include <cuda_runtime.h>
#include <math.h>
#include <stdint.h>

#define MAX_NODES 50000
#define MAX_EDGES 1600000
#define C_IN 256
#define C_OUT 10

typedef unsigned int u32;

// Scratch (static __device__ — no allocation allowed)
__device__ float g_agg1[(size_t)MAX_NODES * C_IN];  // mean-aggregated x
__device__ float g_h[(size_t)MAX_NODES * C_IN];     // hidden activations after relu
__device__ int   g_deg[MAX_NODES];                  // in-degree
__device__ int   g_rowptr[MAX_NODES + 1];           // CSR row pointers (by dst)
__device__ int   g_cursor[MAX_NODES];               // fill cursors
__device__ int   g_srcs[MAX_EDGES];                 // CSR column (src) indices
__device__ float g_p[MAX_NODES * C_OUT];            // h @ W2l  (linearity trick)
__device__ float g_q[MAX_NODES * C_OUT];            // h @ W2r + b2

// ---------------------------------------------------------------------------
// cp.async helpers
// ---------------------------------------------------------------------------
__device__ __forceinline__ void cp_async16(u32 smem_addr, const void* gptr, int src_bytes) {
    asm volatile("cp.async.ca.shared.global [%0], [%1], 16, %2;"
                 :: "r"(smem_addr), "l"(gptr), "r"(src_bytes));
}
__device__ __forceinline__ void cp_commit() {
    asm volatile("cp.async.commit_group;" ::: "memory");
}
__device__ __forceinline__ void cp_wait0() {
    asm volatile("cp.async.wait_group 0;" ::: "memory");
}

// ---------------------------------------------------------------------------
// Degree count (edge_index is int32: [2, E] row-major)
// ---------------------------------------------------------------------------
__global__ void count_k(const int* __restrict__ ei, int E, int M) {
    int e = blockIdx.x * blockDim.x + threadIdx.x;
    if (e >= E) return;
    int dst = __ldg(ei + E + e);
    if ((unsigned)dst < (unsigned)M) atomicAdd(&g_deg[dst], 1);
}

// ---------------------------------------------------------------------------
// Exclusive prefix sum of g_deg -> g_rowptr / g_cursor.  One block, 1024 thr,
// 8 items per thread (7 chunk iterations for 50K).
// ---------------------------------------------------------------------------
__global__ __launch_bounds__(1024) void scan_k(int M) {
    __shared__ int wsum[32];
    __shared__ int s_carry;
    int tid = threadIdx.x, lane = tid & 31, wid = tid >> 5;
    if (tid == 0) s_carry = 0;
    __syncthreads();
    for (int base = 0; base < M; base += 8192) {
        int i0 = base + tid * 8;
        int d[8];
#pragma unroll
        for (int j = 0; j < 8; j++) {
            int i = i0 + j;
            d[j] = (i < M) ? g_deg[i] : 0;
        }
        int tsum = 0;
#pragma unroll
        for (int j = 0; j < 8; j++) { int t = d[j]; d[j] = tsum; tsum += t; }
        int incl = tsum;
#pragma unroll
        for (int o = 1; o < 32; o <<= 1) {
            int t = __shfl_up_sync(0xFFFFFFFFu, incl, o);
            if (lane >= o) incl += t;
        }
        if (lane == 31) wsum[wid] = incl;
        __syncthreads();
        if (wid == 0) {
            int w = wsum[lane];
            int wi = w;
#pragma unroll
            for (int o = 1; o < 32; o <<= 1) {
                int t = __shfl_up_sync(0xFFFFFFFFu, wi, o);
                if (lane >= o) wi += t;
            }
            wsum[lane] = wi - w;
        }
        __syncthreads();
        int texcl = (incl - tsum) + wsum[wid] + s_carry;
#pragma unroll
        for (int j = 0; j < 8; j++) {
            int i = i0 + j;
            if (i < M) { g_rowptr[i] = texcl + d[j]; g_cursor[i] = texcl + d[j]; }
        }
        __syncthreads();
        if (tid == 1023) s_carry = texcl + tsum;
        __syncthreads();
    }
    if (threadIdx.x == 0) g_rowptr[M] = s_carry;
}

// ---------------------------------------------------------------------------
// CSR fill: bucket src ids by dst
// ---------------------------------------------------------------------------
__global__ void fill_k(const int* __restrict__ ei, int E, int M) {
    int e = blockIdx.x * blockDim.x + threadIdx.x;
    if (e >= E) return;
    int src = __ldg(ei + e);
    int dst = __ldg(ei + E + e);
    if ((unsigned)dst >= (unsigned)M) return;
    int pos = atomicAdd(&g_cursor[dst], 1);
    g_srcs[pos] = src;
}

// ---------------------------------------------------------------------------
// Layer-1 mean aggregation: warp per dst node, 8-edge unroll with
// front-batched index loads -> 16 outstanding LDG.128 gathers.
// ---------------------------------------------------------------------------
__global__ __launch_bounds__(256) void agg1_csr_k(const float* __restrict__ x, int M) {
    int node = blockIdx.x * 8 + (threadIdx.x >> 5);
    if (node >= M) return;
    int lane = threadIdx.x & 31;
    int beg = __ldg(g_rowptr + node);
    int end = __ldg(g_rowptr + node + 1);
    float4 a0 = make_float4(0.f, 0.f, 0.f, 0.f);
    float4 a1 = a0;
    int e = beg;
    for (; e + 8 <= end; e += 8) {
        int s[8];
#pragma unroll
        for (int j = 0; j < 8; j++) s[j] = __ldg(g_srcs + e + j);
        float4 t0[8], t1[8];
#pragma unroll
        for (int j = 0; j < 8; j++) {
            const float4* p = (const float4*)(x + (size_t)s[j] * C_IN);
            t0[j] = __ldg(p + lane);
            t1[j] = __ldg(p + lane + 32);
        }
#pragma unroll
        for (int j = 0; j < 8; j++) {
            a0.x += t0[j].x; a0.y += t0[j].y; a0.z += t0[j].z; a0.w += t0[j].w;
            a1.x += t1[j].x; a1.y += t1[j].y; a1.z += t1[j].z; a1.w += t1[j].w;
        }
    }
    for (; e < end; e++) {
        int s = __ldg(g_srcs + e);
        const float4* p = (const float4*)(x + (size_t)s * C_IN);
        float4 v0 = __ldg(p + lane), v1 = __ldg(p + lane + 32);
        a0.x += v0.x; a0.y += v0.y; a0.z += v0.z; a0.w += v0.w;
        a1.x += v1.x; a1.y += v1.y; a1.z += v1.z; a1.w += v1.w;
    }
    float r = 1.0f / fmaxf((float)(end - beg), 1.0f);
    a0.x *= r; a0.y *= r; a0.z *= r; a0.w *= r;
    a1.x *= r; a1.y *= r; a1.z *= r; a1.w *= r;
    float4* outp = (float4*)(g_agg1 + (size_t)node * C_IN);
    outp[lane] = a0;
    outp[lane + 32] = a1;
}

// ---------------------------------------------------------------------------
// GEMM1 (tensor cores, tf32): h = relu(agg @ W1l + x @ W1r + b1).
// K=512 (two sources). 128x128 block tile, BK=16, 8 warps x (32x64) warp
// tiles, mma.sync.m16n8k8.tf32 with raw-fp32 operands (hw truncates to tf32).
// cp.async double-buffered mainloop, 1 barrier per tile.
// Smem conflict-free: As stride 20, Bs stride 136.
// ---------------------------------------------------------------------------
__global__ __launch_bounds__(256) void gemm1_k(const float* __restrict__ x,
                                               const float* __restrict__ Wl,
                                               const float* __restrict__ Wr,
                                               const float* __restrict__ b1, int M) {
    __shared__ float As[2][128][20];
    __shared__ float Bs[2][16][136];
    int tid = threadIdx.x;
    int wid = tid >> 5, lane = tid & 31;
    int grp = lane >> 2, tig = lane & 3;
    int warp_m = (wid & 3) << 5;     // 0,32,64,96
    int warp_n = (wid >> 2) << 6;    // 0,64
    int row0 = blockIdx.y << 7;
    int col0 = blockIdx.x << 7;

    int ar = tid >> 1;               // A row 0..127
    int ah = (tid & 1) << 3;         // A k offset 0 or 8
    int bkk = tid >> 4;              // B k row 0..15
    int bn = (tid & 15) << 3;        // B n offset 0..120
    bool arow_ok = (row0 + ar) < M;
    int a_bytes = arow_ok ? 16 : 0;

    u32 as_base0 = (u32)__cvta_generic_to_shared(&As[0][ar][ah]);
    u32 as_base1 = (u32)__cvta_generic_to_shared(&As[1][ar][ah]);
    u32 bs_base0 = (u32)__cvta_generic_to_shared(&Bs[0][bkk][bn]);
    u32 bs_base1 = (u32)__cvta_generic_to_shared(&Bs[1][bkk][bn]);

    float c[2][8][4];
#pragma unroll
    for (int i = 0; i < 2; i++)
#pragma unroll
        for (int j = 0; j < 8; j++)
#pragma unroll
            for (int r = 0; r < 4; r++) c[i][j][r] = 0.f;

    // issue copy of tile `it` into buffer `buf`
    auto issue_tile = [&](int it, int buf) {
        int kt = it << 4;
        const float* A = (kt < 256) ? g_agg1 : x;
        const float* W = (kt < 256) ? Wl : Wr;
        int kk = kt & 255;
        const float* ap = A + (size_t)(row0 + ar) * 256 + kk + ah;
        u32 as_addr = buf ? as_base1 : as_base0;
        cp_async16(as_addr, ap, a_bytes);
        cp_async16(as_addr + 16, ap + 4, a_bytes);
        const float* wp = W + (size_t)(kk + bkk) * 256 + col0 + bn;
        u32 bs_addr = buf ? bs_base1 : bs_base0;
        cp_async16(bs_addr, wp, 16);
        cp_async16(bs_addr + 16, wp + 4, 16);
        cp_commit();
    };

    issue_tile(0, 0);

    for (int it = 0; it < 32; it++) {
        int cur = it & 1;
        cp_wait0();
        __syncthreads();
        if (it + 1 < 32) issue_tile(it + 1, (it + 1) & 1);

#pragma unroll
        for (int s = 0; s < 2; s++) {
            int k8 = s << 3;
            u32 a[2][4], b[8][2];
#pragma unroll
            for (int mt = 0; mt < 2; mt++) {
                int m0 = warp_m + (mt << 4) + grp;
                a[mt][0] = __float_as_uint(As[cur][m0    ][k8 + tig]);
                a[mt][1] = __float_as_uint(As[cur][m0 + 8][k8 + tig]);
                a[mt][2] = __float_as_uint(As[cur][m0    ][k8 + tig + 4]);
                a[mt][3] = __float_as_uint(As[cur][m0 + 8][k8 + tig + 4]);
            }
#pragma unroll
            for (int nt = 0; nt < 8; nt++) {
                int n0 = warp_n + (nt << 3) + grp;
                b[nt][0] = __float_as_uint(Bs[cur][k8 + tig    ][n0]);
                b[nt][1] = __float_as_uint(Bs[cur][k8 + tig + 4][n0]);
            }
#pragma unroll
            for (int mt = 0; mt < 2; mt++)
#pragma unroll
                for (int nt = 0; nt < 8; nt++) {
                    asm volatile(
                        "mma.sync.aligned.m16n8k8.row.col.f32.tf32.tf32.f32 "
                        "{%0,%1,%2,%3}, {%4,%5,%6,%7}, {%8,%9}, {%0,%1,%2,%3};"
                        : "+f"(c[mt][nt][0]), "+f"(c[mt][nt][1]),
                          "+f"(c[mt][nt][2]), "+f"(c[mt][nt][3])
                        : "r"(a[mt][0]), "r"(a[mt][1]), "r"(a[mt][2]), "r"(a[mt][3]),
                          "r"(b[nt][0]), "r"(b[nt][1]));
                }
        }
    }

    // Epilogue: bias + relu, float2 stores
#pragma unroll
    for (int nt = 0; nt < 8; nt++) {
        int col = col0 + warp_n + (nt << 3) + (tig << 1);
        float bx = __ldg(b1 + col);
        float by = __ldg(b1 + col + 1);
#pragma unroll
        for (int mt = 0; mt < 2; mt++) {
            int r0 = row0 + warp_m + (mt << 4) + grp;
            if (r0 < M) {
                float2 v;
                v.x = fmaxf(c[mt][nt][0] + bx, 0.f);
                v.y = fmaxf(c[mt][nt][1] + by, 0.f);
                *(float2*)(g_h + (size_t)r0 * 256 + col) = v;
            }
            if (r0 + 8 < M) {
                float2 v;
                v.x = fmaxf(c[mt][nt][2] + bx, 0.f);
                v.y = fmaxf(c[mt][nt][3] + by, 0.f);
                *(float2*)(g_h + (size_t)(r0 + 8) * 256 + col) = v;
            }
        }
    }
}

// ---------------------------------------------------------------------------
// Layer 2 small GEMMs: p = h@W2l, q = h@W2r + b2.  Warp per node.
// ---------------------------------------------------------------------------
__global__ __launch_bounds__(256) void gemm2_k(const float* __restrict__ W2l,
                                               const float* __restrict__ W2r,
                                               const float* __restrict__ b2, int M) {
    __shared__ float sWl[C_IN * C_OUT];
    __shared__ float sWr[C_IN * C_OUT];
    for (int i = threadIdx.x; i < C_IN * C_OUT; i += 256) {
        sWl[i] = W2l[i];
        sWr[i] = W2r[i];
    }
    __syncthreads();
    int node = (int)(((size_t)blockIdx.x * blockDim.x + threadIdx.x) >> 5);
    if (node >= M) return;
    int lane = threadIdx.x & 31;
    const float* hr = g_h + (size_t)node * C_IN;
    float hv[8];
#pragma unroll
    for (int j = 0; j < 8; j++) hv[j] = hr[lane + 32 * j];
#pragma unroll
    for (int n = 0; n < C_OUT; n++) {
        float sl = 0.f, sr = 0.f;
#pragma unroll
        for (int j = 0; j < 8; j++) {
            int k = lane + 32 * j;
            sl += hv[j] * sWl[k * C_OUT + n];
            sr += hv[j] * sWr[k * C_OUT + n];
        }
#pragma unroll
        for (int o = 16; o > 0; o >>= 1) {
            sl += __shfl_xor_sync(0xFFFFFFFFu, sl, o);
            sr += __shfl_xor_sync(0xFFFFFFFFu, sr, o);
        }
        if (lane == 0) {
            g_p[node * C_OUT + n] = sl;
            g_q[node * C_OUT + n] = sr + b2[n];
        }
    }
}

// ---------------------------------------------------------------------------
// Fused layer-2 aggregation + log_softmax: warp per node over CSR.
// out = log_softmax(mean_agg(p) + q)
// ---------------------------------------------------------------------------
__global__ __launch_bounds__(256) void agg2_final_k(float* __restrict__ out, int M) {
    int node = blockIdx.x * 8 + (threadIdx.x >> 5);
    if (node >= M) return;
    int lane = threadIdx.x & 31;
    int beg = __ldg(g_rowptr + node);
    int end = __ldg(g_rowptr + node + 1);
    float acc[C_OUT];
#pragma unroll
    for (int i = 0; i < C_OUT; i++) acc[i] = 0.f;
    for (int e = beg + lane; e < end; e += 32) {
        int s = __ldg(g_srcs + e);
        const float2* ps = (const float2*)(g_p + s * C_OUT);
#pragma unroll
        for (int i = 0; i < 5; i++) {
            float2 v = __ldg(ps + i);
            acc[2 * i] += v.x;
            acc[2 * i + 1] += v.y;
        }
    }
#pragma unroll
    for (int i = 0; i < C_OUT; i++)
#pragma unroll
        for (int o = 16; o > 0; o >>= 1)
            acc[i] += __shfl_xor_sync(0xFFFFFFFFu, acc[i], o);
    if (lane == 0) {
        float r = 1.0f / fmaxf((float)(end - beg), 1.0f);
        const float* qp = g_q + node * C_OUT;
        float v[C_OUT];
        float m = -1e30f;
#pragma unroll
        for (int i = 0; i < C_OUT; i++) {
            v[i] = acc[i] * r + qp[i];
            m = fmaxf(m, v[i]);
        }
        float s = 0.f;
#pragma unroll
        for (int i = 0; i < C_OUT; i++) s += expf(v[i] - m);
        float lse = logf(s) + m;
        float2* op = (float2*)(out + node * C_OUT);
#pragma unroll
        for (int i = 0; i < 5; i++)
            op[i] = make_float2(v[2 * i] - lse, v[2 * i + 1] - lse);
    }
}

// ---------------------------------------------------------------------------
// Launch
// ---------------------------------------------------------------------------
extern "C" void kernel_launch(void* const* d_in, const int* in_sizes, int n_in,
                              void* d_out, int out_size) {
    const float* x   = (const float*)d_in[0];
    const int* ei    = (const int*)d_in[1];   // int32 (JAX x64 disabled)
    const float* W1l = (const float*)d_in[2];
    const float* W1r = (const float*)d_in[3];
    const float* b1  = (const float*)d_in[4];
    const float* W2l = (const float*)d_in[5];
    const float* W2r = (const float*)d_in[6];
    const float* b2  = (const float*)d_in[7];
    float* out       = (float*)d_out;

    int M = in_sizes[0] / C_IN;   // 50000
    int E = in_sizes[1] / 2;      // 1600000
    if (E > MAX_EDGES) E = MAX_EDGES;

    void* p_deg;
    cudaGetSymbolAddress(&p_deg, g_deg);
    cudaMemsetAsync(p_deg, 0, (size_t)M * sizeof(int));

    count_k<<<(E + 255) / 256, 256>>>(ei, E, M);
    scan_k<<<1, 1024>>>(M);
    fill_k<<<(E + 255) / 256, 256>>>(ei, E, M);
    agg1_csr_k<<<(M + 7) / 8, 256>>>(x, M);
    dim3 g1(2, (M + 127) / 128);
    gemm1_k<<<g1, 256>>>(x, W1l, W1r, b1, M);
    gemm2_k<<<(M + 7) / 8, 256>>>(W2l, W2r, b2, M);
    agg2_final_k<<<(M + 7) / 8, 256>>>(out, M);
}